// round 2
// baseline (speedup 1.0000x reference)
#include <cuda_runtime.h>
#include <math.h>

#define N 49
#define CH 128
#define NH 4
#define DH 32
#define NPAD 64

// shared memory layout (float offsets)
#define OFF_H    0            // [64][128] hidden (rows 49..63 zeroed)
#define OFF_W    8192         // [128][129] weight staging (pitch 129 -> conflict-free col reads)
#define OFF_S    8192         // [4][49][52] scores, overlays W region after QKV
#define OFF_Q    24704        // [49][128]
#define OFF_KT   30976        // [128][53]  K transposed (pitch 53, coprime with 32)
#define OFF_V    37760        // [49][128]
#define OFF_MASK 44032        // [49*49]
#define SMEM_FLOATS 46433     // 185,732 bytes

__device__ float g_bias[NH * N * N];  // [h][i][j] relative position bias, shared by all windows

// Dtype-robust bias gather: the reference declares int64 indices but JAX
// (x64 disabled) silently emits int32. Detect at runtime: scanning the first
// 2401 int32 words is safe for both layouts; int64-LE data has ALL odd words
// zero (indices < 169), int32 data has ~99% nonzero odd words.
__global__ void bias_gather_kernel(const float* __restrict__ table,
                                   const void* __restrict__ idx_raw) {
    __shared__ int is32;
    const int* i32 = (const int*)idx_raw;
    if (threadIdx.x == 0) is32 = 0;
    __syncthreads();
    int any = 0;
    for (int t = threadIdx.x; t < N * N; t += blockDim.x)
        if ((t & 1) && i32[t] != 0) any = 1;
    if (any) is32 = 1;
    __syncthreads();
    const int stride = is32 ? 1 : 2;  // int64-LE: low word at even positions
    for (int t = threadIdx.x; t < N * N; t += blockDim.x) {
        int e = i32[t * stride];
#pragma unroll
        for (int h = 0; h < NH; h++)
            g_bias[h * (N * N) + t] = table[e * NH + h];
    }
}

__global__ void __launch_bounds__(512, 1)
swin_attn_kernel(const float* __restrict__ hs,
                 const float* __restrict__ mask,
                 const float* __restrict__ Wq, const float* __restrict__ bq,
                 const float* __restrict__ Wk, const float* __restrict__ bk,
                 const float* __restrict__ Wv, const float* __restrict__ bvp,
                 float* __restrict__ out)
{
    extern __shared__ float smem[];
    const int b = blockIdx.x;
    const int t = threadIdx.x;
    const int lane = t & 31;
    const int warp = t >> 5;

    float* sH  = smem + OFF_H;
    float* sW  = smem + OFF_W;
    float* sS  = smem + OFF_S;
    float* sQ  = smem + OFF_Q;
    float* sKt = smem + OFF_KT;
    float* sV  = smem + OFF_V;
    float* sM  = smem + OFF_MASK;

    // ---- load hidden (zero-pad rows 49..63) and mask ----
    const float* hsb = hs + (size_t)b * (N * CH);
    for (int e = t; e < NPAD * CH; e += 512)
        sH[e] = (e < N * CH) ? hsb[e] : 0.0f;
    const float* mb = mask + (size_t)b * (N * N);
    for (int e = t; e < N * N; e += 512)
        sM[e] = mb[e];

    // ---- QKV projections: y[n][d] = sum_c h[n][c] * W[d][c] + bias[d] ----
    const float* Wmat[3] = {Wq, Wk, Wv};
    const float* bvec[3] = {bq, bk, bvp};
    const int nbase = warp * 4;  // warps 0..12 compute (n coverage 0..51), 13..15 idle

#pragma unroll
    for (int m = 0; m < 3; m++) {
        __syncthreads();  // prior compute done before overwriting sW (and sH ready, iter 0)
        const float* W = Wmat[m];
        for (int e = t; e < CH * CH; e += 512) {
            int d = e >> 7;
            int c = e & 127;
            sW[d * 129 + c] = W[e];  // coalesced LDG, conflict-free STS
        }
        __syncthreads();
        if (nbase < N) {
            const float* bb = bvec[m];
            float br[4];
#pragma unroll
            for (int r = 0; r < 4; r++) br[r] = bb[lane + 32 * r];
            float acc[4][4];
#pragma unroll
            for (int ni = 0; ni < 4; ni++)
#pragma unroll
                for (int r = 0; r < 4; r++) acc[ni][r] = br[r];

            const float* w0p = sW + lane * 129;   // d = lane + 32r rows
            const float* hp  = sH + nbase * CH;
#pragma unroll 4
            for (int c = 0; c < CH; c++) {
                float w0 = w0p[c];
                float w1 = w0p[32 * 129 + c];
                float w2 = w0p[64 * 129 + c];
                float w3 = w0p[96 * 129 + c];
#pragma unroll
                for (int ni = 0; ni < 4; ni++) {
                    float hv = hp[ni * CH + c];   // broadcast
                    acc[ni][0] += hv * w0;
                    acc[ni][1] += hv * w1;
                    acc[ni][2] += hv * w2;
                    acc[ni][3] += hv * w3;
                }
            }
#pragma unroll
            for (int ni = 0; ni < 4; ni++) {
                int n = nbase + ni;
                if (n < N) {
                    if (m == 0) {
#pragma unroll
                        for (int r = 0; r < 4; r++)
                            sQ[n * CH + lane + 32 * r] = acc[ni][r];
                    } else if (m == 1) {
#pragma unroll
                        for (int r = 0; r < 4; r++)
                            sKt[(lane + 32 * r) * 53 + n] = acc[ni][r];  // conflict-free (53 odd-coprime)
                    } else {
#pragma unroll
                        for (int r = 0; r < 4; r++)
                            sV[n * CH + lane + 32 * r] = acc[ni][r];
                    }
                }
            }
        }
    }
    __syncthreads();

    // ---- scores: S[h][i][j] = qk/sqrt(32) + bias + mask ----
    const float rscale = 0.17677669529663687f;  // 1/sqrt(32)
    {
        int iu[4];
#pragma unroll
        for (int u = 0; u < 4; u++) {
            int i = warp + 16 * u;
            iu[u] = (i < N) ? i : (N - 1);  // clamp to avoid OOB; store guarded below
        }
#pragma unroll
        for (int h = 0; h < NH; h++) {
            const float* kcol = sKt + (h * DH) * 53 + lane;
            float a0[4] = {0.f, 0.f, 0.f, 0.f};
            float a1[4] = {0.f, 0.f, 0.f, 0.f};
#pragma unroll
            for (int d = 0; d < DH; d++) {
                float k0 = kcol[d * 53];         // j = lane
                float k1 = kcol[d * 53 + 32];    // j = lane + 32 (garbage beyond 48; store guarded)
#pragma unroll
                for (int u = 0; u < 4; u++) {
                    float q = sQ[iu[u] * CH + h * DH + d];  // broadcast
                    a0[u] += q * k0;
                    a1[u] += q * k1;
                }
            }
#pragma unroll
            for (int u = 0; u < 4; u++) {
                int i = warp + 16 * u;
                if (i < N) {
                    int j0 = lane;
                    sS[(h * N + i) * 52 + j0] = a0[u] * rscale
                        + g_bias[h * (N * N) + i * N + j0] + sM[i * N + j0];
                    int j1 = lane + 32;
                    if (j1 < N)
                        sS[(h * N + i) * 52 + j1] = a1[u] * rscale
                            + g_bias[h * (N * N) + i * N + j1] + sM[i * N + j1];
                }
            }
        }
    }
    __syncthreads();

    // ---- softmax over j, one thread per (h,i) row ----
    if (t < NH * N) {
        float* row = sS + t * 52;
        float mx = -1e30f;
        for (int j = 0; j < N; j++) mx = fmaxf(mx, row[j]);
        float sum = 0.f;
        for (int j = 0; j < N; j++) {
            float e = __expf(row[j] - mx);
            row[j] = e;
            sum += e;
        }
        float inv = 1.0f / sum;
        for (int j = 0; j < N; j++) row[j] *= inv;
    }
    __syncthreads();

    // ---- ctx: out[i][c] = sum_j P[h][i][j] * V[j][c],  h = c/32 ----
    {
        const int c  = t & 127;
        const int ig = t >> 7;     // 0..3
        const int h  = c >> 5;     // uniform per warp
        float ctxa[13];
#pragma unroll
        for (int k = 0; k < 13; k++) ctxa[k] = 0.f;
        const float* prow = sS + (h * N) * 52;
#pragma unroll 7
        for (int j = 0; j < N; j++) {
            float v = sV[j * CH + c];          // conflict-free
#pragma unroll
            for (int k = 0; k < 13; k++) {
                int i = ig + 4 * k;
                if (i < N) ctxa[k] += prow[i * 52 + j] * v;  // P broadcast
            }
        }
        float* ob = out + (size_t)b * (N * CH);
#pragma unroll
        for (int k = 0; k < 13; k++) {
            int i = ig + 4 * k;
            if (i < N) ob[i * CH + c] = ctxa[k];  // coalesced
        }
    }
}

extern "C" void kernel_launch(void* const* d_in, const int* in_sizes, int n_in,
                              void* d_out, int out_size) {
    const float* hs    = (const float*)d_in[0];
    const float* mask  = (const float*)d_in[1];
    const float* Wq    = (const float*)d_in[2];
    const float* bq    = (const float*)d_in[3];
    const float* Wk    = (const float*)d_in[4];
    const float* bk    = (const float*)d_in[5];
    const float* Wv    = (const float*)d_in[6];
    const float* bv    = (const float*)d_in[7];
    const float* table = (const float*)d_in[8];
    const void*  idx   = (const void*)d_in[9];
    float* out = (float*)d_out;

    int B = in_sizes[0] / (N * CH);

    bias_gather_kernel<<<1, 256>>>(table, idx);

    size_t smem_bytes = SMEM_FLOATS * sizeof(float);
    cudaFuncSetAttribute(swin_attn_kernel,
                         cudaFuncAttributeMaxDynamicSharedMemorySize,
                         (int)smem_bytes);
    swin_attn_kernel<<<B, 512, smem_bytes>>>(hs, mask, Wq, bq, Wk, bk, Wv, bv, out);
}

// round 6
// speedup vs baseline: 1.2435x; 1.2435x over previous
#include <cuda_runtime.h>
#include <cuda_bf16.h>
#include <cstdint>
#include <math.h>

#define N 49
#define CH 128
#define NH 4
#define DH 32
#define MAXTOK (4096 * 49)

// ============================ scratch ============================
__device__ float g_q[(size_t)CH * MAXTOK];   // [d][token]
__device__ float g_k[(size_t)CH * MAXTOK];   // [d][token]
__device__ float g_v[(size_t)CH * MAXTOK];   // [d][token]
__device__ float g_bias[NH * N * N];

// ============================ helpers ============================
__device__ __forceinline__ uint32_t smem_u32(const void* p) {
    uint32_t a;
    asm("{ .reg .u64 t; cvta.to.shared.u64 t, %1; cvt.u32.u64 %0, t; }" : "=r"(a) : "l"(p));
    return a;
}
__device__ __forceinline__ void ldsm_x4(uint32_t* r, uint32_t addr) {
    asm volatile("ldmatrix.sync.aligned.m8n8.x4.shared.b16 {%0,%1,%2,%3}, [%4];"
        : "=r"(r[0]), "=r"(r[1]), "=r"(r[2]), "=r"(r[3]) : "r"(addr));
}
__device__ __forceinline__ void mma16816(float* c, const uint32_t* a, uint32_t b0, uint32_t b1) {
    asm volatile(
        "mma.sync.aligned.m16n8k16.row.col.f32.bf16.bf16.f32 "
        "{%0,%1,%2,%3}, {%4,%5,%6,%7}, {%8,%9}, {%0,%1,%2,%3};"
        : "+f"(c[0]), "+f"(c[1]), "+f"(c[2]), "+f"(c[3])
        : "r"(a[0]), "r"(a[1]), "r"(a[2]), "r"(a[3]), "r"(b0), "r"(b1));
}

// ============================ bias gather ============================
// dtype-robust: reference declares int64 indices but JAX (x64 off) emits int32.
__global__ void bias_gather_kernel(const float* __restrict__ table,
                                   const void* __restrict__ idx_raw) {
    __shared__ int is32;
    const int* i32 = (const int*)idx_raw;
    if (threadIdx.x == 0) is32 = 0;
    __syncthreads();
    int any = 0;
    for (int t = threadIdx.x; t < N * N; t += blockDim.x)
        if ((t & 1) && i32[t] != 0) any = 1;
    if (any) is32 = 1;
    __syncthreads();
    const int stride = is32 ? 1 : 2;
    for (int t = threadIdx.x; t < N * N; t += blockDim.x) {
        int e = i32[t * stride];
#pragma unroll
        for (int h = 0; h < NH; h++)
            g_bias[h * (N * N) + t] = table[e * NH + h];
    }
}

// ============================ QKV GEMM (mma.sync bf16 hi/lo) ============================
// Row = 128 bf16 = 256 bytes; PITCH = 272 B (16B pad -> ldmatrix conflict-free:
// 8 consecutive rows differ by 17 chunks, 17 mod 8 = 1).
#define PITCHB 272
#define TILE_B (128 * PITCHB)       // 34816
#define GOFF_AHI 0
#define GOFF_ALO (TILE_B)           // 34816
#define GOFF_BHI (2 * TILE_B)       // 69632
#define GOFF_BLO (3 * TILE_B)       // 104448
#define GOFF_BIAS (4 * TILE_B)      // 139264
#define GSMEM_BYTES (GOFF_BIAS + 512)  // 139776

__device__ __forceinline__ void cvt_tile_g(const float2* __restrict__ src, int valid_rows,
                                           char* s_hi, char* s_lo, int tid) {
    for (int e = tid; e < 128 * 64; e += 256) {
        int row = e >> 6, kp = e & 63;   // kp indexes bf16 pairs (2 cols)
        float2 x = (row < valid_rows) ? src[row * 64 + kp] : make_float2(0.f, 0.f);
        __nv_bfloat16 h0 = __float2bfloat16(x.x);
        __nv_bfloat16 h1 = __float2bfloat16(x.y);
        __nv_bfloat16 l0 = __float2bfloat16(x.x - __bfloat162float(h0));
        __nv_bfloat16 l1 = __float2bfloat16(x.y - __bfloat162float(h1));
        __nv_bfloat162 hv = __halves2bfloat162(h0, h1);
        __nv_bfloat162 lv = __halves2bfloat162(l0, l1);
        int off = row * PITCHB + kp * 4;
        *reinterpret_cast<uint32_t*>(s_hi + off) = *reinterpret_cast<uint32_t*>(&hv);
        *reinterpret_cast<uint32_t*>(s_lo + off) = *reinterpret_cast<uint32_t*>(&lv);
    }
}

__global__ void __launch_bounds__(256, 1)
qkv_gemm_kernel(const float* __restrict__ hs,
                const float* __restrict__ Wq, const float* __restrict__ bq,
                const float* __restrict__ Wk, const float* __restrict__ bk,
                const float* __restrict__ Wv, const float* __restrict__ bv,
                int tot)
{
    extern __shared__ char smem[];
    const int tid = threadIdx.x;
    const int warp = tid >> 5;
    const int lane = tid & 31;
    const int tileBase = blockIdx.x * 128;
    const int valid = min(128, tot - tileBase);

    float* sBias = reinterpret_cast<float*>(smem + GOFF_BIAS);
    const uint32_t sb = smem_u32(smem);

    // A tile: hidden rows [tileBase, tileBase+valid)
    cvt_tile_g(reinterpret_cast<const float2*>(hs + (size_t)tileBase * CH), valid,
               smem + GOFF_AHI, smem + GOFF_ALO, tid);

    const float* Ws[3] = {Wq, Wk, Wv};
    const float* bs[3] = {bq, bk, bv};
    float* outs[3] = {g_q, g_k, g_v};

    // ldmatrix lane addressing (bytes)
    const uint32_t a_row = (uint32_t)((lane & 7) + ((lane >> 3) & 1) * 8);
    const uint32_t a_kb  = (uint32_t)((lane >> 4) * 16);          // +8 bf16 cols
    const uint32_t b_row = (uint32_t)((lane & 7) + (lane >> 4) * 8);
    const uint32_t b_kb  = (uint32_t)(((lane >> 3) & 1) * 16);

    const int g  = lane >> 2;
    const int tg = lane & 3;
    const int token0 = tileBase + warp * 16 + g;
    const int token1 = token0 + 8;

#pragma unroll 1
    for (int m = 0; m < 3; m++) {
        __syncthreads();  // prior iteration's B reads / bias reads complete
        cvt_tile_g(reinterpret_cast<const float2*>(Ws[m]), 128,
                   smem + GOFF_BHI, smem + GOFF_BLO, tid);
        if (tid < 128) sBias[tid] = bs[m][tid];
        __syncthreads();

        float acc[16][4];
#pragma unroll
        for (int nt = 0; nt < 16; nt++)
#pragma unroll
            for (int r = 0; r < 4; r++) acc[nt][r] = 0.f;

        const uint32_t aHiBase = sb + GOFF_AHI + (warp * 16 + a_row) * PITCHB + a_kb;
        const uint32_t aLoBase = aHiBase + (GOFF_ALO - GOFF_AHI);
        const uint32_t bHiBase = sb + GOFF_BHI + b_row * PITCHB + b_kb;
        const uint32_t bLoBase = bHiBase + (GOFF_BLO - GOFF_BHI);

#pragma unroll 1
        for (int ks = 0; ks < 8; ks++) {
            uint32_t ah[4], al[4];
            ldsm_x4(ah, aHiBase + ks * 32);
            ldsm_x4(al, aLoBase + ks * 32);
#pragma unroll
            for (int nt2 = 0; nt2 < 8; nt2++) {
                uint32_t bh[4], bl[4];
                uint32_t bo = (uint32_t)(nt2 * 16 * PITCHB + ks * 32);
                ldsm_x4(bh, bHiBase + bo);
                ldsm_x4(bl, bLoBase + bo);
                mma16816(acc[2 * nt2],     ah, bh[0], bh[1]);
                mma16816(acc[2 * nt2 + 1], ah, bh[2], bh[3]);
                mma16816(acc[2 * nt2],     ah, bl[0], bl[1]);
                mma16816(acc[2 * nt2 + 1], ah, bl[2], bl[3]);
                mma16816(acc[2 * nt2],     al, bh[0], bh[1]);
                mma16816(acc[2 * nt2 + 1], al, bh[2], bh[3]);
            }
        }

        // epilogue: D[row=token within tile][col=d]; write [d][token] + bias
        float* ob = outs[m];
#pragma unroll
        for (int nt = 0; nt < 16; nt++) {
            int n = nt * 8 + 2 * tg;
            float b0 = sBias[n], b1 = sBias[n + 1];
            if (token0 < tot) {
                ob[(size_t)n * tot + token0]       = acc[nt][0] + b0;
                ob[(size_t)(n + 1) * tot + token0] = acc[nt][1] + b1;
            }
            if (token1 < tot) {
                ob[(size_t)n * tot + token1]       = acc[nt][2] + b0;
                ob[(size_t)(n + 1) * tot + token1] = acc[nt][3] + b1;
            }
        }
    }
}

// ============================ attention kernel ============================
// smem float offsets
#define AQT 0                  // [128][53] Q^T
#define AKT 6784               // [128][53] K^T
#define AV  13568              // [49][132] V
#define AS  20036              // [4][49][52] scores
#define AM  30228              // [49*49] mask
#define ATOT_F 32629           // 130,516 bytes

__global__ void __launch_bounds__(512, 1)
attn_kernel(const float* __restrict__ mask, float* __restrict__ out, int tot)
{
    extern __shared__ float sf[];
    const int b = blockIdx.x;
    const int t = threadIdx.x;
    const int lane = t & 31;
    const int warp = t >> 5;

    float* sQt = sf + AQT;
    float* sKt = sf + AKT;
    float* sV  = sf + AV;
    float* sS  = sf + AS;
    float* sM  = sf + AM;

    const size_t tb = (size_t)b * N;  // token base
    for (int e = t; e < CH * N; e += 512) {
        int d = e / N, n = e - d * N;
        size_t gidx = (size_t)d * tot + tb + n;
        sQt[d * 53 + n] = g_q[gidx];
        sKt[d * 53 + n] = g_k[gidx];
        sV[n * 132 + d] = g_v[gidx];
    }
    const float* mb = mask + (size_t)b * (N * N);
    for (int e = t; e < N * N; e += 512)
        sM[e] = mb[e];
    __syncthreads();

    // ---- scores ----
    const float rscale = 0.17677669529663687f;  // 1/sqrt(32)
    {
        int iu[4];
#pragma unroll
        for (int u = 0; u < 4; u++) {
            int i = warp + 16 * u;
            iu[u] = (i < N) ? i : (N - 1);
        }
#pragma unroll
        for (int h = 0; h < NH; h++) {
            const float* kcol = sKt + (h * DH) * 53 + lane;
            const float* qrow = sQt + (h * DH) * 53;
            float a0[4] = {0.f, 0.f, 0.f, 0.f};
            float a1[4] = {0.f, 0.f, 0.f, 0.f};
#pragma unroll
            for (int d = 0; d < DH; d++) {
                float k0 = kcol[d * 53];
                float k1 = kcol[d * 53 + 32];  // garbage beyond j=48; stores guarded
#pragma unroll
                for (int u = 0; u < 4; u++) {
                    float q = qrow[d * 53 + iu[u]];  // broadcast
                    a0[u] += q * k0;
                    a1[u] += q * k1;
                }
            }
#pragma unroll
            for (int u = 0; u < 4; u++) {
                int i = warp + 16 * u;
                if (i < N) {
                    int j0 = lane;
                    sS[(h * N + i) * 52 + j0] = a0[u] * rscale
                        + g_bias[h * (N * N) + i * N + j0] + sM[i * N + j0];
                    int j1 = lane + 32;
                    if (j1 < N)
                        sS[(h * N + i) * 52 + j1] = a1[u] * rscale
                            + g_bias[h * (N * N) + i * N + j1] + sM[i * N + j1];
                }
            }
        }
    }
    __syncthreads();

    // ---- softmax ----
    if (t < NH * N) {
        float* row = sS + t * 52;
        float mx = -1e30f;
        for (int j = 0; j < N; j++) mx = fmaxf(mx, row[j]);
        float sum = 0.f;
        for (int j = 0; j < N; j++) {
            float e = __expf(row[j] - mx);
            row[j] = e;
            sum += e;
        }
        float inv = 1.0f / sum;
        for (int j = 0; j < N; j++) row[j] *= inv;
    }
    __syncthreads();

    // ---- ctx ----
    {
        const int c4 = t & 31;        // c = 4*c4 .. 4*c4+3
        const int ig = t >> 5;        // 0..15
        const int h = c4 >> 3;
        float acc[4][4];
#pragma unroll
        for (int kk = 0; kk < 4; kk++)
#pragma unroll
            for (int r = 0; r < 4; r++) acc[kk][r] = 0.f;

#pragma unroll 7
        for (int j = 0; j < N; j++) {
            float4 v = *reinterpret_cast<const float4*>(&sV[j * 132 + c4 * 4]);
#pragma unroll
            for (int kk = 0; kk < 4; kk++) {
                int i = ig + 16 * kk;
                if (i < N) {
                    float p = sS[(h * N + i) * 52 + j];
                    acc[kk][0] += p * v.x;
                    acc[kk][1] += p * v.y;
                    acc[kk][2] += p * v.z;
                    acc[kk][3] += p * v.w;
                }
            }
        }
        float* ob = out + tb * CH;
#pragma unroll
        for (int kk = 0; kk < 4; kk++) {
            int i = ig + 16 * kk;
            if (i < N) {
                float4 o = make_float4(acc[kk][0], acc[kk][1], acc[kk][2], acc[kk][3]);
                *reinterpret_cast<float4*>(&ob[i * CH + c4 * 4]) = o;
            }
        }
    }
}

// ============================ launch ============================
extern "C" void kernel_launch(void* const* d_in, const int* in_sizes, int n_in,
                              void* d_out, int out_size) {
    const float* hs    = (const float*)d_in[0];
    const float* mask  = (const float*)d_in[1];
    const float* Wq    = (const float*)d_in[2];
    const float* bq    = (const float*)d_in[3];
    const float* Wk    = (const float*)d_in[4];
    const float* bk    = (const float*)d_in[5];
    const float* Wv    = (const float*)d_in[6];
    const float* bv    = (const float*)d_in[7];
    const float* table = (const float*)d_in[8];
    const void*  idx   = (const void*)d_in[9];
    float* out = (float*)d_out;

    int B = in_sizes[0] / (N * CH);
    int tot = B * N;

    cudaFuncSetAttribute(qkv_gemm_kernel, cudaFuncAttributeMaxDynamicSharedMemorySize,
                         GSMEM_BYTES);
    cudaFuncSetAttribute(attn_kernel, cudaFuncAttributeMaxDynamicSharedMemorySize,
                         ATOT_F * (int)sizeof(float));

    bias_gather_kernel<<<1, 256>>>(table, idx);

    int tiles = (tot + 127) / 128;
    qkv_gemm_kernel<<<tiles, 256, GSMEM_BYTES>>>(hs, Wq, bq, Wk, bk, Wv, bv, tot);
    attn_kernel<<<B, 512, ATOT_F * sizeof(float)>>>(mask, out, tot);
}

// round 7
// speedup vs baseline: 1.4647x; 1.1779x over previous
#include <cuda_runtime.h>
#include <cuda_fp16.h>
#include <cstdint>
#include <math.h>

#define N 49
#define CH 128
#define NH 4
#define DH 32
#define MAXTOK (4096 * 49)

// ============================ scratch ============================
__device__ float g_q[(size_t)CH * MAXTOK];   // [d][token]
__device__ float g_k[(size_t)CH * MAXTOK];   // [d][token]
__device__ float g_v[(size_t)CH * MAXTOK];   // [d][token]
__device__ float g_bias[NH * N * N];

// ============================ helpers ============================
__device__ __forceinline__ uint32_t smem_u32(const void* p) {
    uint32_t a;
    asm("{ .reg .u64 t; cvta.to.shared.u64 t, %1; cvt.u32.u64 %0, t; }" : "=r"(a) : "l"(p));
    return a;
}
__device__ __forceinline__ void ldsm_x4(uint32_t* r, uint32_t addr) {
    asm volatile("ldmatrix.sync.aligned.m8n8.x4.shared.b16 {%0,%1,%2,%3}, [%4];"
        : "=r"(r[0]), "=r"(r[1]), "=r"(r[2]), "=r"(r[3]) : "r"(addr));
}
__device__ __forceinline__ void mma16816f16(float* c, const uint32_t* a, uint32_t b0, uint32_t b1) {
    asm volatile(
        "mma.sync.aligned.m16n8k16.row.col.f32.f16.f16.f32 "
        "{%0,%1,%2,%3}, {%4,%5,%6,%7}, {%8,%9}, {%0,%1,%2,%3};"
        : "+f"(c[0]), "+f"(c[1]), "+f"(c[2]), "+f"(c[3])
        : "r"(a[0]), "r"(a[1]), "r"(a[2]), "r"(a[3]), "r"(b0), "r"(b1));
}

// ============================ QKV GEMM (mma.sync fp16 single-pass) ============================
// Row = 128 fp16 = 256 bytes; PITCH = 272 B (8 consecutive rows differ by 17
// 16B-chunks, 17 mod 8 = 1 -> ldmatrix conflict-free).
#define PITCHB 272
#define TILE_B (128 * PITCHB)          // 34816
#define GOFF_A   0
#define GOFF_B   (TILE_B)              // 34816
#define GOFF_BIAS (2 * TILE_B)         // 69632
#define GSMEM_BYTES (GOFF_BIAS + 512)  // 70144

__device__ __forceinline__ void cvt_tile_h(const float2* __restrict__ src, int valid_rows,
                                           char* s_dst, int tid) {
    for (int e = tid; e < 128 * 64; e += 256) {
        int row = e >> 6, kp = e & 63;   // kp indexes fp16 pairs
        float2 x = (row < valid_rows) ? src[row * 64 + kp] : make_float2(0.f, 0.f);
        __half2 hv = __halves2half2(__float2half(x.x), __float2half(x.y));
        *reinterpret_cast<uint32_t*>(s_dst + row * PITCHB + kp * 4) =
            *reinterpret_cast<uint32_t*>(&hv);
    }
}

__global__ void __launch_bounds__(256, 2)
qkv_gemm_kernel(const float* __restrict__ hs,
                const float* __restrict__ Wq, const float* __restrict__ bq,
                const float* __restrict__ Wk, const float* __restrict__ bk,
                const float* __restrict__ Wv, const float* __restrict__ bv,
                const float* __restrict__ table, const void* __restrict__ idx_raw,
                int tot)
{
    extern __shared__ char smem[];
    const int tid = threadIdx.x;
    const int warp = tid >> 5;
    const int lane = tid & 31;
    const int tileBase = blockIdx.x * 128;
    const int valid = min(128, tot - tileBase);

    // -------- block 0 also performs the bias gather (dtype-robust) --------
    // reference declares int64 indices but JAX (x64 off) emits int32; int64-LE
    // data has all odd 32-bit words zero (indices < 169).
    if (blockIdx.x == 0) {
        __shared__ int is32;
        const int* i32 = (const int*)idx_raw;
        if (tid == 0) is32 = 0;
        __syncthreads();
        int any = 0;
        for (int t = tid; t < N * N; t += 256)
            if ((t & 1) && i32[t] != 0) any = 1;
        if (any) is32 = 1;
        __syncthreads();
        const int stride = is32 ? 1 : 2;
        for (int t = tid; t < N * N; t += 256) {
            int e = i32[t * stride];
#pragma unroll
            for (int h = 0; h < NH; h++)
                g_bias[h * (N * N) + t] = table[e * NH + h];
        }
    }

    float* sBias = reinterpret_cast<float*>(smem + GOFF_BIAS);
    const uint32_t sb = smem_u32(smem);

    // A tile: hidden rows [tileBase, tileBase+valid)
    cvt_tile_h(reinterpret_cast<const float2*>(hs + (size_t)tileBase * CH), valid,
               smem + GOFF_A, tid);

    const float* Ws[3] = {Wq, Wk, Wv};
    const float* bs[3] = {bq, bk, bv};
    float* outs[3] = {g_q, g_k, g_v};

    // ldmatrix lane addressing (bytes)
    const uint32_t a_row = (uint32_t)((lane & 7) + ((lane >> 3) & 1) * 8);
    const uint32_t a_kb  = (uint32_t)((lane >> 4) * 16);
    const uint32_t b_row = (uint32_t)((lane & 7) + (lane >> 4) * 8);
    const uint32_t b_kb  = (uint32_t)(((lane >> 3) & 1) * 16);

    const int g  = lane >> 2;
    const int tg = lane & 3;
    const int token0 = tileBase + warp * 16 + g;
    const int token1 = token0 + 8;

#pragma unroll 1
    for (int m = 0; m < 3; m++) {
        __syncthreads();  // prior iteration's B/bias reads complete
        cvt_tile_h(reinterpret_cast<const float2*>(Ws[m]), 128, smem + GOFF_B, tid);
        if (tid < 128) sBias[tid] = bs[m][tid];
        __syncthreads();

        float acc[16][4];
#pragma unroll
        for (int nt = 0; nt < 16; nt++)
#pragma unroll
            for (int r = 0; r < 4; r++) acc[nt][r] = 0.f;

        const uint32_t aBase = sb + GOFF_A + (warp * 16 + a_row) * PITCHB + a_kb;
        const uint32_t bBase = sb + GOFF_B + b_row * PITCHB + b_kb;

#pragma unroll 1
        for (int ks = 0; ks < 8; ks++) {
            uint32_t ah[4];
            ldsm_x4(ah, aBase + ks * 32);
#pragma unroll
            for (int nt2 = 0; nt2 < 8; nt2++) {
                uint32_t bh[4];
                ldsm_x4(bh, bBase + (uint32_t)(nt2 * 16 * PITCHB + ks * 32));
                mma16816f16(acc[2 * nt2],     ah, bh[0], bh[1]);
                mma16816f16(acc[2 * nt2 + 1], ah, bh[2], bh[3]);
            }
        }

        // epilogue: D[row=token within tile][col=d]; write [d][token] + bias
        float* ob = outs[m];
#pragma unroll
        for (int nt = 0; nt < 16; nt++) {
            int n = nt * 8 + 2 * tg;
            float b0 = sBias[n], b1 = sBias[n + 1];
            if (token0 < tot) {
                ob[(size_t)n * tot + token0]       = acc[nt][0] + b0;
                ob[(size_t)(n + 1) * tot + token0] = acc[nt][1] + b1;
            }
            if (token1 < tot) {
                ob[(size_t)n * tot + token1]       = acc[nt][2] + b0;
                ob[(size_t)(n + 1) * tot + token1] = acc[nt][3] + b1;
            }
        }
    }
}

// ============================ attention kernel ============================
// smem float offsets
#define AQT 0                  // [128][53] Q^T
#define AKT 6784               // [128][53] K^T
#define AV  13568              // [49][132] V
#define AS  20036              // [4][49][52] scores
#define AM  30228              // [49*49] mask
#define ATOT_F 32629           // 130,516 bytes

__global__ void __launch_bounds__(512, 1)
attn_kernel(const float* __restrict__ mask, float* __restrict__ out, int tot)
{
    extern __shared__ float sf[];
    const int b = blockIdx.x;
    const int t = threadIdx.x;
    const int lane = t & 31;
    const int warp = t >> 5;

    float* sQt = sf + AQT;
    float* sKt = sf + AKT;
    float* sV  = sf + AV;
    float* sS  = sf + AS;
    float* sM  = sf + AM;

    const size_t tb = (size_t)b * N;  // token base
    for (int e = t; e < CH * N; e += 512) {
        int d = e / N, n = e - d * N;
        size_t gidx = (size_t)d * tot + tb + n;
        sQt[d * 53 + n] = g_q[gidx];
        sKt[d * 53 + n] = g_k[gidx];
        sV[n * 132 + d] = g_v[gidx];
    }
    const float* mb = mask + (size_t)b * (N * N);
    for (int e = t; e < N * N; e += 512)
        sM[e] = mb[e];
    __syncthreads();

    // ---- scores ----
    const float rscale = 0.17677669529663687f;  // 1/sqrt(32)
    {
        int iu[4];
#pragma unroll
        for (int u = 0; u < 4; u++) {
            int i = warp + 16 * u;
            iu[u] = (i < N) ? i : (N - 1);
        }
#pragma unroll
        for (int h = 0; h < NH; h++) {
            const float* kcol = sKt + (h * DH) * 53 + lane;
            const float* qrow = sQt + (h * DH) * 53;
            float a0[4] = {0.f, 0.f, 0.f, 0.f};
            float a1[4] = {0.f, 0.f, 0.f, 0.f};
#pragma unroll
            for (int d = 0; d < DH; d++) {
                float k0 = kcol[d * 53];
                float k1 = kcol[d * 53 + 32];  // garbage beyond j=48; stores guarded
#pragma unroll
                for (int u = 0; u < 4; u++) {
                    float q = qrow[d * 53 + iu[u]];  // broadcast
                    a0[u] += q * k0;
                    a1[u] += q * k1;
                }
            }
#pragma unroll
            for (int u = 0; u < 4; u++) {
                int i = warp + 16 * u;
                if (i < N) {
                    int j0 = lane;
                    sS[(h * N + i) * 52 + j0] = a0[u] * rscale
                        + g_bias[h * (N * N) + i * N + j0] + sM[i * N + j0];
                    int j1 = lane + 32;
                    if (j1 < N)
                        sS[(h * N + i) * 52 + j1] = a1[u] * rscale
                            + g_bias[h * (N * N) + i * N + j1] + sM[i * N + j1];
                }
            }
        }
    }
    __syncthreads();

    // ---- softmax ----
    if (t < NH * N) {
        float* row = sS + t * 52;
        float mx = -1e30f;
        for (int j = 0; j < N; j++) mx = fmaxf(mx, row[j]);
        float sum = 0.f;
        for (int j = 0; j < N; j++) {
            float e = __expf(row[j] - mx);
            row[j] = e;
            sum += e;
        }
        float inv = 1.0f / sum;
        for (int j = 0; j < N; j++) row[j] *= inv;
    }
    __syncthreads();

    // ---- ctx ----
    {
        const int c4 = t & 31;        // c = 4*c4 .. 4*c4+3
        const int ig = t >> 5;        // 0..15
        const int h = c4 >> 3;
        float acc[4][4];
#pragma unroll
        for (int kk = 0; kk < 4; kk++)
#pragma unroll
            for (int r = 0; r < 4; r++) acc[kk][r] = 0.f;

#pragma unroll 7
        for (int j = 0; j < N; j++) {
            float4 v = *reinterpret_cast<const float4*>(&sV[j * 132 + c4 * 4]);
#pragma unroll
            for (int kk = 0; kk < 4; kk++) {
                int i = ig + 16 * kk;
                if (i < N) {
                    float p = sS[(h * N + i) * 52 + j];
                    acc[kk][0] += p * v.x;
                    acc[kk][1] += p * v.y;
                    acc[kk][2] += p * v.z;
                    acc[kk][3] += p * v.w;
                }
            }
        }
        float* ob = out + tb * CH;
#pragma unroll
        for (int kk = 0; kk < 4; kk++) {
            int i = ig + 16 * kk;
            if (i < N) {
                float4 o = make_float4(acc[kk][0], acc[kk][1], acc[kk][2], acc[kk][3]);
                *reinterpret_cast<float4*>(&ob[i * CH + c4 * 4]) = o;
            }
        }
    }
}

// ============================ launch ============================
extern "C" void kernel_launch(void* const* d_in, const int* in_sizes, int n_in,
                              void* d_out, int out_size) {
    const float* hs    = (const float*)d_in[0];
    const float* mask  = (const float*)d_in[1];
    const float* Wq    = (const float*)d_in[2];
    const float* bq    = (const float*)d_in[3];
    const float* Wk    = (const float*)d_in[4];
    const float* bk    = (const float*)d_in[5];
    const float* Wv    = (const float*)d_in[6];
    const float* bv    = (const float*)d_in[7];
    const float* table = (const float*)d_in[8];
    const void*  idx   = (const void*)d_in[9];
    float* out = (float*)d_out;

    int B = in_sizes[0] / (N * CH);
    int tot = B * N;

    cudaFuncSetAttribute(qkv_gemm_kernel, cudaFuncAttributeMaxDynamicSharedMemorySize,
                         GSMEM_BYTES);
    cudaFuncSetAttribute(attn_kernel, cudaFuncAttributeMaxDynamicSharedMemorySize,
                         ATOT_F * (int)sizeof(float));

    int tiles = (tot + 127) / 128;
    qkv_gemm_kernel<<<tiles, 256, GSMEM_BYTES>>>(hs, Wq, bq, Wk, bk, Wv, bv,
                                                 table, idx, tot);
    attn_kernel<<<B, 512, ATOT_F * sizeof(float)>>>(mask, out, tot);
}

// round 8
// speedup vs baseline: 2.3231x; 1.5861x over previous
#include <cuda_runtime.h>
#include <cuda_fp16.h>
#include <cstdint>
#include <math.h>

#define N 49
#define CH 128
#define NH 4
#define DH 32
#define MAXTOK (4096 * 49)

// ============================ scratch ============================
// q/k/v packed half2 over d-pairs: word w = (val[2*d2], val[2*d2+1]) at [d2][token]
__device__ uint32_t g_q2[(size_t)64 * MAXTOK];
__device__ uint32_t g_k2[(size_t)64 * MAXTOK];
__device__ uint32_t g_v2[(size_t)64 * MAXTOK];
__device__ float g_bias[NH * N * N];

// ============================ helpers ============================
__device__ __forceinline__ uint32_t smem_u32(const void* p) {
    uint32_t a;
    asm("{ .reg .u64 t; cvta.to.shared.u64 t, %1; cvt.u32.u64 %0, t; }" : "=r"(a) : "l"(p));
    return a;
}
__device__ __forceinline__ void ldsm_x4(uint32_t* r, uint32_t addr) {
    asm volatile("ldmatrix.sync.aligned.m8n8.x4.shared.b16 {%0,%1,%2,%3}, [%4];"
        : "=r"(r[0]), "=r"(r[1]), "=r"(r[2]), "=r"(r[3]) : "r"(addr));
}
__device__ __forceinline__ void mma16816f16(float* c, const uint32_t* a, uint32_t b0, uint32_t b1) {
    asm volatile(
        "mma.sync.aligned.m16n8k16.row.col.f32.f16.f16.f32 "
        "{%0,%1,%2,%3}, {%4,%5,%6,%7}, {%8,%9}, {%0,%1,%2,%3};"
        : "+f"(c[0]), "+f"(c[1]), "+f"(c[2]), "+f"(c[3])
        : "r"(a[0]), "r"(a[1]), "r"(a[2]), "r"(a[3]), "r"(b0), "r"(b1));
}
__device__ __forceinline__ uint32_t pack_h2(float a, float b) {
    __half2 h = __floats2half2_rn(a, b);
    return *reinterpret_cast<uint32_t*>(&h);
}
__device__ __forceinline__ float2 unpack_h2(uint32_t w) {
    __half2 h = *reinterpret_cast<__half2*>(&w);
    return __half22float2(h);
}

// ============================ QKV GEMM (mma.sync fp16 single-pass) ============================
#define PITCHB 272
#define TILE_B (128 * PITCHB)          // 34816
#define GOFF_A   0
#define GOFF_B   (TILE_B)
#define GOFF_BIAS (2 * TILE_B)
#define GSMEM_BYTES (GOFF_BIAS + 512)  // 70144

__device__ __forceinline__ void cvt_tile_h(const float2* __restrict__ src, int valid_rows,
                                           char* s_dst, int tid) {
    for (int e = tid; e < 128 * 64; e += 256) {
        int row = e >> 6, kp = e & 63;
        float2 x = (row < valid_rows) ? src[row * 64 + kp] : make_float2(0.f, 0.f);
        *reinterpret_cast<uint32_t*>(s_dst + row * PITCHB + kp * 4) = pack_h2(x.x, x.y);
    }
}

__global__ void __launch_bounds__(256, 2)
qkv_gemm_kernel(const float* __restrict__ hs,
                const float* __restrict__ Wq, const float* __restrict__ bq,
                const float* __restrict__ Wk, const float* __restrict__ bk,
                const float* __restrict__ Wv, const float* __restrict__ bv,
                const float* __restrict__ table, const void* __restrict__ idx_raw,
                int tot)
{
    extern __shared__ char smem[];
    const int tid = threadIdx.x;
    const int warp = tid >> 5;
    const int lane = tid & 31;
    const int tileBase = blockIdx.x * 128;
    const int valid = min(128, tot - tileBase);

    // block 0 also performs the dtype-robust bias gather (int64-declared
    // indices that JAX (x64 off) actually emits as int32)
    if (blockIdx.x == 0) {
        __shared__ int is32;
        const int* i32 = (const int*)idx_raw;
        if (tid == 0) is32 = 0;
        __syncthreads();
        int any = 0;
        for (int t = tid; t < N * N; t += 256)
            if ((t & 1) && i32[t] != 0) any = 1;
        if (any) is32 = 1;
        __syncthreads();
        const int stride = is32 ? 1 : 2;
        for (int t = tid; t < N * N; t += 256) {
            int e = i32[t * stride];
#pragma unroll
            for (int h = 0; h < NH; h++)
                g_bias[h * (N * N) + t] = table[e * NH + h];
        }
    }

    float* sBias = reinterpret_cast<float*>(smem + GOFF_BIAS);
    const uint32_t sb = smem_u32(smem);

    cvt_tile_h(reinterpret_cast<const float2*>(hs + (size_t)tileBase * CH), valid,
               smem + GOFF_A, tid);

    const float* Ws[3] = {Wq, Wk, Wv};
    const float* bs[3] = {bq, bk, bv};
    uint32_t* outs[3] = {g_q2, g_k2, g_v2};

    const uint32_t a_row = (uint32_t)((lane & 7) + ((lane >> 3) & 1) * 8);
    const uint32_t a_kb  = (uint32_t)((lane >> 4) * 16);
    const uint32_t b_row = (uint32_t)((lane & 7) + (lane >> 4) * 8);
    const uint32_t b_kb  = (uint32_t)(((lane >> 3) & 1) * 16);

    const int g  = lane >> 2;
    const int tg = lane & 3;
    const int token0 = tileBase + warp * 16 + g;
    const int token1 = token0 + 8;

#pragma unroll 1
    for (int m = 0; m < 3; m++) {
        __syncthreads();
        cvt_tile_h(reinterpret_cast<const float2*>(Ws[m]), 128, smem + GOFF_B, tid);
        if (tid < 128) sBias[tid] = bs[m][tid];
        __syncthreads();

        float acc[16][4];
#pragma unroll
        for (int nt = 0; nt < 16; nt++)
#pragma unroll
            for (int r = 0; r < 4; r++) acc[nt][r] = 0.f;

        const uint32_t aBase = sb + GOFF_A + (warp * 16 + a_row) * PITCHB + a_kb;
        const uint32_t bBase = sb + GOFF_B + b_row * PITCHB + b_kb;

#pragma unroll 1
        for (int ks = 0; ks < 8; ks++) {
            uint32_t ah[4];
            ldsm_x4(ah, aBase + ks * 32);
#pragma unroll
            for (int nt2 = 0; nt2 < 8; nt2++) {
                uint32_t bh[4];
                ldsm_x4(bh, bBase + (uint32_t)(nt2 * 16 * PITCHB + ks * 32));
                mma16816f16(acc[2 * nt2],     ah, bh[0], bh[1]);
                mma16816f16(acc[2 * nt2 + 1], ah, bh[2], bh[3]);
            }
        }

        // epilogue: acc[nt][0],[1] = D[token0][n],[n+1] (n even) -> pack half2 word at [n/2][token]
        uint32_t* ob = outs[m];
#pragma unroll
        for (int nt = 0; nt < 16; nt++) {
            int n = nt * 8 + 2 * tg;
            int d2 = n >> 1;
            float b0 = sBias[n], b1 = sBias[n + 1];
            if (token0 < tot)
                ob[(size_t)d2 * tot + token0] = pack_h2(acc[nt][0] + b0, acc[nt][1] + b1);
            if (token1 < tot)
                ob[(size_t)d2 * tot + token1] = pack_h2(acc[nt][2] + b0, acc[nt][3] + b1);
        }
    }
}

// ============================ attention kernel ============================
// smem word offsets (uint32 units)
#define AQ2 0                     // [64][53] q half2 words
#define AK2 3392                  // [64][53]
#define AV2 6784                  // [49][66] v half2 words (pitch 66: uint2-aligned)
#define AS2 10018                 // scores fp32 [4][49][50]
#define AM2 19818                 // mask fp32 [2401]
#define ATOT_W 22219              // 88,876 bytes

__global__ void __launch_bounds__(512, 2)
attn_kernel(const float* __restrict__ mask, float* __restrict__ out, int tot)
{
    extern __shared__ uint32_t sw[];
    const int b = blockIdx.x;
    const int t = threadIdx.x;
    const int lane = t & 31;
    const int warp = t >> 5;

    uint32_t* sQ2 = sw + AQ2;
    uint32_t* sK2 = sw + AK2;
    uint32_t* sV2 = sw + AV2;
    float* sS = reinterpret_cast<float*>(sw + AS2);
    float* sM = reinterpret_cast<float*>(sw + AM2);

    const size_t tb = (size_t)b * N;

    // ---- loads (all straight word copies, coalesced LDG) ----
    for (int e = t; e < 64 * 64; e += 512) {
        int n = e & 63, d2 = e >> 6;
        if (n < N) {
            size_t gi = (size_t)d2 * tot + tb + n;
            sQ2[d2 * 53 + n] = g_q2[gi];
            sK2[d2 * 53 + n] = g_k2[gi];
            sV2[n * 66 + d2] = g_v2[gi];
        }
    }
    const float* mb = mask + (size_t)b * (N * N);
    for (int e = t; e < N * N; e += 512)
        sM[e] = mb[e];
    __syncthreads();

    // ---- scores: warp = (head, 13-row i-chunk) ----
    const float rscale = 0.17677669529663687f;
    {
        const int h  = warp >> 2;
        const int i0 = (warp & 3) * 13;
        float acc0[13], acc1[13];
#pragma unroll
        for (int ii = 0; ii < 13; ii++) { acc0[ii] = 0.f; acc1[ii] = 0.f; }

        const uint32_t* krow = sK2 + h * 16 * 53;
        const uint32_t* qrow = sQ2 + h * 16 * 53;
#pragma unroll
        for (int d2 = 0; d2 < 16; d2++) {
            float2 k0 = unpack_h2(krow[d2 * 53 + lane]);
            float2 k1 = unpack_h2(krow[d2 * 53 + lane + 32]);  // garbage beyond j=48; guarded
#pragma unroll
            for (int ii = 0; ii < 13; ii++) {
                float2 q = unpack_h2(qrow[d2 * 53 + i0 + ii]);  // broadcast (i0+ii<=51<53)
                acc0[ii] += q.x * k0.x + q.y * k0.y;
                acc1[ii] += q.x * k1.x + q.y * k1.y;
            }
        }
#pragma unroll
        for (int ii = 0; ii < 13; ii++) {
            int i = i0 + ii;
            if (i < N) {
                int j0 = lane;
                sS[(h * N + i) * 50 + j0] = acc0[ii] * rscale
                    + g_bias[h * (N * N) + i * N + j0] + sM[i * N + j0];
                int j1 = lane + 32;
                if (j1 < N)
                    sS[(h * N + i) * 50 + j1] = acc1[ii] * rscale
                        + g_bias[h * (N * N) + i * N + j1] + sM[i * N + j1];
            }
        }
    }
    __syncthreads();

    // ---- softmax (one thread per (h,i) row) ----
    if (t < NH * N) {
        float* row = sS + t * 50;
        float mx = -1e30f;
        for (int j = 0; j < N; j++) mx = fmaxf(mx, row[j]);
        float sum = 0.f;
        for (int j = 0; j < N; j++) {
            float e = __expf(row[j] - mx);
            row[j] = e;
            sum += e;
        }
        float inv = 1.0f / sum;
        for (int j = 0; j < N; j++) row[j] *= inv;
    }
    __syncthreads();

    // ---- ctx: lane c-quad, V half2 pairs ----
    {
        const int c4 = t & 31;        // c = 4*c4..4*c4+3 -> d2 pair (2*c4, 2*c4+1)
        const int ig = t >> 5;        // 0..15
        const int h = c4 >> 3;
        float acc[4][4];
#pragma unroll
        for (int kk = 0; kk < 4; kk++)
#pragma unroll
            for (int r = 0; r < 4; r++) acc[kk][r] = 0.f;

        const float* prow = sS + (h * N) * 50;
#pragma unroll 7
        for (int j = 0; j < N; j++) {
            uint2 vw = *reinterpret_cast<const uint2*>(&sV2[j * 66 + c4 * 2]);
            float2 va = unpack_h2(vw.x);
            float2 vb = unpack_h2(vw.y);
#pragma unroll
            for (int kk = 0; kk < 4; kk++) {
                int i = ig + 16 * kk;
                if (i < N) {
                    float p = prow[i * 50 + j];
                    acc[kk][0] += p * va.x;
                    acc[kk][1] += p * va.y;
                    acc[kk][2] += p * vb.x;
                    acc[kk][3] += p * vb.y;
                }
            }
        }
        float* ob = out + tb * CH;
#pragma unroll
        for (int kk = 0; kk < 4; kk++) {
            int i = ig + 16 * kk;
            if (i < N) {
                float4 o = make_float4(acc[kk][0], acc[kk][1], acc[kk][2], acc[kk][3]);
                *reinterpret_cast<float4*>(&ob[i * CH + c4 * 4]) = o;
            }
        }
    }
}

// ============================ launch ============================
extern "C" void kernel_launch(void* const* d_in, const int* in_sizes, int n_in,
                              void* d_out, int out_size) {
    const float* hs    = (const float*)d_in[0];
    const float* mask  = (const float*)d_in[1];
    const float* Wq    = (const float*)d_in[2];
    const float* bq    = (const float*)d_in[3];
    const float* Wk    = (const float*)d_in[4];
    const float* bk    = (const float*)d_in[5];
    const float* Wv    = (const float*)d_in[6];
    const float* bv    = (const float*)d_in[7];
    const float* table = (const float*)d_in[8];
    const void*  idx   = (const void*)d_in[9];
    float* out = (float*)d_out;

    int B = in_sizes[0] / (N * CH);
    int tot = B * N;

    cudaFuncSetAttribute(qkv_gemm_kernel, cudaFuncAttributeMaxDynamicSharedMemorySize,
                         GSMEM_BYTES);
    cudaFuncSetAttribute(attn_kernel, cudaFuncAttributeMaxDynamicSharedMemorySize,
                         ATOT_W * (int)sizeof(uint32_t));

    int tiles = (tot + 127) / 128;
    qkv_gemm_kernel<<<tiles, 256, GSMEM_BYTES>>>(hs, Wq, bq, Wk, bk, Wv, bv,
                                                 table, idx, tot);
    attn_kernel<<<B, 512, ATOT_W * sizeof(uint32_t)>>>(mask, out, tot);
}

// round 9
// speedup vs baseline: 2.7102x; 1.1666x over previous
#include <cuda_runtime.h>
#include <cuda_fp16.h>
#include <cstdint>
#include <math.h>

#define N 49
#define CH 128
#define NH 4
#define DH 32
#define MAXTOK (4096 * 49)

// ============================ scratch ============================
__device__ uint32_t g_q2[(size_t)64 * MAXTOK];  // half2 (d,d+1) at [d2][token]
__device__ uint32_t g_k2[(size_t)64 * MAXTOK];
__device__ uint32_t g_v2[(size_t)64 * MAXTOK];
__device__ float g_bias[NH * N * N];

// ============================ helpers ============================
__device__ __forceinline__ uint32_t smem_u32(const void* p) {
    uint32_t a;
    asm("{ .reg .u64 t; cvta.to.shared.u64 t, %1; cvt.u32.u64 %0, t; }" : "=r"(a) : "l"(p));
    return a;
}
__device__ __forceinline__ void ldsm_x4(uint32_t* r, uint32_t addr) {
    asm volatile("ldmatrix.sync.aligned.m8n8.x4.shared.b16 {%0,%1,%2,%3}, [%4];"
        : "=r"(r[0]), "=r"(r[1]), "=r"(r[2]), "=r"(r[3]) : "r"(addr));
}
__device__ __forceinline__ void mma16816f16(float* c, const uint32_t* a, uint32_t b0, uint32_t b1) {
    asm volatile(
        "mma.sync.aligned.m16n8k16.row.col.f32.f16.f16.f32 "
        "{%0,%1,%2,%3}, {%4,%5,%6,%7}, {%8,%9}, {%0,%1,%2,%3};"
        : "+f"(c[0]), "+f"(c[1]), "+f"(c[2]), "+f"(c[3])
        : "r"(a[0]), "r"(a[1]), "r"(a[2]), "r"(a[3]), "r"(b0), "r"(b1));
}
__device__ __forceinline__ uint32_t pack_h2(float a, float b) {
    __half2 h = __floats2half2_rn(a, b);
    return *reinterpret_cast<uint32_t*>(&h);
}

// ============================ QKV GEMM (mma.sync fp16) ============================
#define PITCHB 272
#define TILE_B (128 * PITCHB)          // 34816
#define GOFF_A   0
#define GOFF_B   (TILE_B)              // B tile; staging overlays after MMAs
#define GOFF_BIAS (2 * TILE_B)
#define GSMEM_BYTES (GOFF_BIAS + 512)  // 70144

__device__ __forceinline__ void cvt_tile_h(const float2* __restrict__ src, int valid_rows,
                                           char* s_dst, int tid) {
    for (int e = tid; e < 128 * 64; e += 256) {
        int row = e >> 6, kp = e & 63;
        float2 x = (row < valid_rows) ? src[row * 64 + kp] : make_float2(0.f, 0.f);
        *reinterpret_cast<uint32_t*>(s_dst + row * PITCHB + kp * 4) = pack_h2(x.x, x.y);
    }
}

__global__ void __launch_bounds__(256, 2)
qkv_gemm_kernel(const float* __restrict__ hs,
                const float* __restrict__ Wq, const float* __restrict__ bq,
                const float* __restrict__ Wk, const float* __restrict__ bk,
                const float* __restrict__ Wv, const float* __restrict__ bv,
                const float* __restrict__ table, const void* __restrict__ idx_raw,
                int tot)
{
    extern __shared__ char smem[];
    const int tid = threadIdx.x;
    const int warp = tid >> 5;
    const int lane = tid & 31;
    const int tileBase = blockIdx.x * 128;
    const int valid = min(128, tot - tileBase);

    // block 0 also does the dtype-robust bias gather (int64-declared indices
    // that JAX with x64 disabled actually emits as int32)
    if (blockIdx.x == 0) {
        __shared__ int is32;
        const int* i32 = (const int*)idx_raw;
        if (tid == 0) is32 = 0;
        __syncthreads();
        int any = 0;
        for (int t = tid; t < N * N; t += 256)
            if ((t & 1) && i32[t] != 0) any = 1;
        if (any) is32 = 1;
        __syncthreads();
        const int stride = is32 ? 1 : 2;
        for (int t = tid; t < N * N; t += 256) {
            int e = i32[t * stride];
#pragma unroll
            for (int h = 0; h < NH; h++)
                g_bias[h * (N * N) + t] = table[e * NH + h];
        }
    }

    float* sBias = reinterpret_cast<float*>(smem + GOFF_BIAS);
    uint32_t* staging = reinterpret_cast<uint32_t*>(smem + GOFF_B);  // [128][65] words
    const uint32_t sb = smem_u32(smem);

    cvt_tile_h(reinterpret_cast<const float2*>(hs + (size_t)tileBase * CH), valid,
               smem + GOFF_A, tid);

    const float* Ws[3] = {Wq, Wk, Wv};
    const float* bs[3] = {bq, bk, bv};
    uint32_t* outs[3] = {g_q2, g_k2, g_v2};

    const uint32_t a_row = (uint32_t)((lane & 7) + ((lane >> 3) & 1) * 8);
    const uint32_t a_kb  = (uint32_t)((lane >> 4) * 16);
    const uint32_t b_row = (uint32_t)((lane & 7) + (lane >> 4) * 8);
    const uint32_t b_kb  = (uint32_t)(((lane >> 3) & 1) * 16);

    const int g  = lane >> 2;
    const int tg = lane & 3;

#pragma unroll 1
    for (int m = 0; m < 3; m++) {
        __syncthreads();  // staging reads done (prev iter) before B overwrite
        cvt_tile_h(reinterpret_cast<const float2*>(Ws[m]), 128, smem + GOFF_B, tid);
        if (tid < 128) sBias[tid] = bs[m][tid];
        __syncthreads();

        float acc[16][4];
#pragma unroll
        for (int nt = 0; nt < 16; nt++)
#pragma unroll
            for (int r = 0; r < 4; r++) acc[nt][r] = 0.f;

        const uint32_t aBase = sb + GOFF_A + (warp * 16 + a_row) * PITCHB + a_kb;
        const uint32_t bBase = sb + GOFF_B + b_row * PITCHB + b_kb;

#pragma unroll 1
        for (int ks = 0; ks < 8; ks++) {
            uint32_t ah[4];
            ldsm_x4(ah, aBase + ks * 32);
#pragma unroll
            for (int nt2 = 0; nt2 < 8; nt2++) {
                uint32_t bh[4];
                ldsm_x4(bh, bBase + (uint32_t)(nt2 * 16 * PITCHB + ks * 32));
                mma16816f16(acc[2 * nt2],     ah, bh[0], bh[1]);
                mma16816f16(acc[2 * nt2 + 1], ah, bh[2], bh[3]);
            }
        }
        __syncthreads();  // all B reads complete before staging overlays it

        // fragments -> staging [token_local][d2] (d2 = nt*4+tg)
#pragma unroll
        for (int nt = 0; nt < 16; nt++) {
            int n = nt * 8 + 2 * tg;
            int d2 = nt * 4 + tg;
            float b0 = sBias[n], b1 = sBias[n + 1];
            staging[(warp * 16 + g) * 65 + d2]     = pack_h2(acc[nt][0] + b0, acc[nt][1] + b1);
            staging[(warp * 16 + g + 8) * 65 + d2] = pack_h2(acc[nt][2] + b0, acc[nt][3] + b1);
        }
        __syncthreads();

        // coalesced store: per d2, 128 consecutive tokens
        uint32_t* ob = outs[m];
        for (int e = tid; e < 64 * 128; e += 256) {
            int d2 = e >> 7, tk = e & 127;
            if (tileBase + tk < tot)
                ob[(size_t)d2 * tot + tileBase + tk] = staging[tk * 65 + d2];
        }
    }
}

// ============================ attention kernel (mma.sync) ============================
// smem layout (bytes):
//  [0, 20480)      sQ fp16 [h][i 64][d 32] pitch 80B   (later overlaid by sP)
//  [20480, 40960)  sK fp16 [h][j 64][d 32] pitch 80B
//  sP overlay at 0: fp16 [h][i 64][j 64] pitch 144B (36864 <= 40960)
//  [40960, 59392)  sVT fp16 [h][c 32][j 64] pitch 144B
//  [59392, 98592)  sS fp32 [h*49+i][50]
#define AVT_OFF 40960
#define AS_OFF  59392
#define ASMEM_BYTES 98592

__global__ void __launch_bounds__(512, 2)
attn_kernel(const float* __restrict__ mask, float* __restrict__ out, int tot)
{
    extern __shared__ char smem[];
    const uint32_t sb = smem_u32(smem);
    const int b = blockIdx.x;
    const int t = threadIdx.x;
    const int lane = t & 31;
    const int warp = t >> 5;

    uint32_t* sQKw = reinterpret_cast<uint32_t*>(smem);     // Q words at 0, K at +5120 words
    __half*   sVTh = reinterpret_cast<__half*>(smem + AVT_OFF);
    uint32_t* sPw  = reinterpret_cast<uint32_t*>(smem);     // overlay after scores
    float*    sS   = reinterpret_cast<float*>(smem + AS_OFF);

    const size_t tb = (size_t)b * N;
    const float* mb = mask + (size_t)b * (N * N);

    // ---- loads: Q/K word-packed per head (pitch 20 words); V transposed [c][j], j>=49 zeroed ----
    for (int e = t; e < 4096; e += 512) {
        int n = e & 63, d2 = e >> 6;
        int h = d2 >> 4, dd = d2 & 15;
        if (n < N) {
            size_t gi = (size_t)d2 * tot + tb + n;
            sQKw[h * 1280 + n * 20 + dd] = g_q2[gi];
            sQKw[5120 + h * 1280 + n * 20 + dd] = g_k2[gi];
            uint32_t vw = g_v2[gi];
            __half2 vh = *reinterpret_cast<__half2*>(&vw);
            sVTh[h * 2304 + (dd * 2) * 72 + n]     = __low2half(vh);
            sVTh[h * 2304 + (dd * 2 + 1) * 72 + n] = __high2half(vh);
        } else {
            sVTh[h * 2304 + (dd * 2) * 72 + n]     = __float2half(0.f);
            sVTh[h * 2304 + (dd * 2 + 1) * 72 + n] = __float2half(0.f);
        }
    }
    __syncthreads();

    const int h  = warp >> 2;     // head
    const int mt = warp & 3;      // i-tile (16 rows)
    const int g  = lane >> 2;
    const int tg = lane & 3;
    const uint32_t a_row = (uint32_t)((lane & 7) + ((lane >> 3) & 1) * 8);
    const uint32_t a_kb  = (uint32_t)((lane >> 4) * 16);
    const uint32_t b_row = (uint32_t)((lane & 7) + (lane >> 4) * 8);
    const uint32_t b_kb  = (uint32_t)(((lane >> 3) & 1) * 16);
    const float rscale = 0.17677669529663687f;  // 1/sqrt(32)

    // ---- scores: D[i][j] = Q·K^T, fragment epilogue adds scale+bias+mask ----
    {
        float sc[8][4];
#pragma unroll
        for (int nn = 0; nn < 8; nn++)
#pragma unroll
            for (int r = 0; r < 4; r++) sc[nn][r] = 0.f;

        const uint32_t qbase = sb + h * 5120 + (mt * 16 + a_row) * 80 + a_kb;
        const uint32_t kbase = sb + 20480 + h * 5120 + b_row * 80 + b_kb;
#pragma unroll
        for (int kc = 0; kc < 2; kc++) {
            uint32_t ah[4];
            ldsm_x4(ah, qbase + kc * 32);
#pragma unroll
            for (int np = 0; np < 4; np++) {
                uint32_t bh[4];
                ldsm_x4(bh, kbase + (uint32_t)(np * 16 * 80) + kc * 32);
                mma16816f16(sc[2 * np],     ah, bh[0], bh[1]);
                mma16816f16(sc[2 * np + 1], ah, bh[2], bh[3]);
            }
        }
        const int i0 = mt * 16 + g;
        const int i1 = i0 + 8;
#pragma unroll
        for (int nn = 0; nn < 8; nn++) {
            int j = nn * 8 + 2 * tg;
#pragma unroll
            for (int cc = 0; cc < 2; cc++) {
                int jj = j + cc;
                if (jj < N) {
                    if (i0 < N)
                        sS[(h * N + i0) * 50 + jj] = sc[nn][cc] * rscale
                            + g_bias[h * (N * N) + i0 * N + jj] + mb[i0 * N + jj];
                    if (i1 < N)
                        sS[(h * N + i1) * 50 + jj] = sc[nn][2 + cc] * rscale
                            + g_bias[h * (N * N) + i1 * N + jj] + mb[i1 * N + jj];
                }
            }
        }
    }
    __syncthreads();

    // ---- softmax (one thread per (h,i) row) ----
    if (t < NH * N) {
        float* row = sS + t * 50;
        float mx = -1e30f;
        for (int j = 0; j < N; j++) mx = fmaxf(mx, row[j]);
        float sum = 0.f;
        for (int j = 0; j < N; j++) {
            float e = __expf(row[j] - mx);
            row[j] = e;
            sum += e;
        }
        float inv = 1.0f / sum;
        for (int j = 0; j < N; j++) row[j] *= inv;
    }
    __syncthreads();

    // ---- P: fp32 scores -> fp16 [h][i 64][j 64] pitch 144B, zero-padded (overlays Q/K) ----
    for (int e = t; e < 8192; e += 512) {
        int j2 = e & 31;
        int i  = (e >> 5) & 63;
        int hh = e >> 11;
        float v0 = 0.f, v1 = 0.f;
        if (i < N) {
            int j = 2 * j2;
            const float* srow = sS + (hh * N + i) * 50;
            if (j < N)     v0 = srow[j];
            if (j + 1 < N) v1 = srow[j + 1];
        }
        sPw[hh * 2304 + i * 36 + j2] = pack_h2(v0, v1);
    }
    __syncthreads();

    // ---- ctx: D[i][c] = P · V^T ----
    {
        float ct[4][4];
#pragma unroll
        for (int q = 0; q < 4; q++)
#pragma unroll
            for (int r = 0; r < 4; r++) ct[q][r] = 0.f;

        const uint32_t pbase = sb + h * 9216 + (mt * 16 + a_row) * 144 + a_kb;
        const uint32_t vbase = sb + AVT_OFF + h * 4608 + b_row * 144 + b_kb;
#pragma unroll
        for (int kc = 0; kc < 4; kc++) {
            uint32_t ah[4];
            ldsm_x4(ah, pbase + kc * 32);
#pragma unroll
            for (int np = 0; np < 2; np++) {
                uint32_t bh[4];
                ldsm_x4(bh, vbase + (uint32_t)(np * 16 * 144) + kc * 32);
                mma16816f16(ct[2 * np],     ah, bh[0], bh[1]);
                mma16816f16(ct[2 * np + 1], ah, bh[2], bh[3]);
            }
        }
        const int i0 = mt * 16 + g;
        float* ob = out + tb * CH + h * 32;
#pragma unroll
        for (int q = 0; q < 4; q++) {
            int c = q * 8 + 2 * tg;
            if (i0 < N)
                *reinterpret_cast<float2*>(&ob[i0 * CH + c]) = make_float2(ct[q][0], ct[q][1]);
            if (i0 + 8 < N)
                *reinterpret_cast<float2*>(&ob[(i0 + 8) * CH + c]) = make_float2(ct[q][2], ct[q][3]);
        }
    }
}

// ============================ launch ============================
extern "C" void kernel_launch(void* const* d_in, const int* in_sizes, int n_in,
                              void* d_out, int out_size) {
    const float* hs    = (const float*)d_in[0];
    const float* mask  = (const float*)d_in[1];
    const float* Wq    = (const float*)d_in[2];
    const float* bq    = (const float*)d_in[3];
    const float* Wk    = (const float*)d_in[4];
    const float* bk    = (const float*)d_in[5];
    const float* Wv    = (const float*)d_in[6];
    const float* bv    = (const float*)d_in[7];
    const float* table = (const float*)d_in[8];
    const void*  idx   = (const void*)d_in[9];
    float* out = (float*)d_out;

    int B = in_sizes[0] / (N * CH);
    int tot = B * N;

    cudaFuncSetAttribute(qkv_gemm_kernel, cudaFuncAttributeMaxDynamicSharedMemorySize,
                         GSMEM_BYTES);
    cudaFuncSetAttribute(attn_kernel, cudaFuncAttributeMaxDynamicSharedMemorySize,
                         ASMEM_BYTES);

    int tiles = (tot + 127) / 128;
    qkv_gemm_kernel<<<tiles, 256, GSMEM_BYTES>>>(hs, Wq, bq, Wk, bk, Wv, bv,
                                                 table, idx, tot);
    attn_kernel<<<B, 512, ASMEM_BYTES>>>(mask, out, tot);
}

// round 10
// speedup vs baseline: 3.9072x; 1.4417x over previous
#include <cuda_runtime.h>
#include <cuda_fp16.h>
#include <cstdint>
#include <math.h>

#define N 49
#define CH 128
#define NH 4
#define DH 32
#define MAXTOK (4096 * 49)

// ============================ scratch ============================
__device__ uint32_t g_q2[(size_t)64 * MAXTOK];  // half2 (d,d+1) at [d2][token]
__device__ uint32_t g_k2[(size_t)64 * MAXTOK];
__device__ uint32_t g_v2[(size_t)64 * MAXTOK];
__device__ uint32_t g_w2[3][64 * 128];          // weights fp16, half2-packed rows
__device__ float g_bias[NH * N * N];

// ============================ helpers ============================
__device__ __forceinline__ uint32_t smem_u32(const void* p) {
    uint32_t a;
    asm("{ .reg .u64 t; cvta.to.shared.u64 t, %1; cvt.u32.u64 %0, t; }" : "=r"(a) : "l"(p));
    return a;
}
__device__ __forceinline__ void ldsm_x4(uint32_t* r, uint32_t addr) {
    asm volatile("ldmatrix.sync.aligned.m8n8.x4.shared.b16 {%0,%1,%2,%3}, [%4];"
        : "=r"(r[0]), "=r"(r[1]), "=r"(r[2]), "=r"(r[3]) : "r"(addr));
}
__device__ __forceinline__ void mma16816f16(float* c, const uint32_t* a, uint32_t b0, uint32_t b1) {
    asm volatile(
        "mma.sync.aligned.m16n8k16.row.col.f32.f16.f16.f32 "
        "{%0,%1,%2,%3}, {%4,%5,%6,%7}, {%8,%9}, {%0,%1,%2,%3};"
        : "+f"(c[0]), "+f"(c[1]), "+f"(c[2]), "+f"(c[3])
        : "r"(a[0]), "r"(a[1]), "r"(a[2]), "r"(a[3]), "r"(b0), "r"(b1));
}
__device__ __forceinline__ uint32_t pack_h2(float a, float b) {
    __half2 h = __floats2half2_rn(a, b);
    return *reinterpret_cast<uint32_t*>(&h);
}

// ============================ prep: weight cvt + bias gather ============================
__global__ void prep_kernel(const float* __restrict__ Wq, const float* __restrict__ Wk,
                            const float* __restrict__ Wv,
                            const float* __restrict__ table, const void* __restrict__ idx_raw) {
    const int m = blockIdx.x;
    const int tid = threadIdx.x;
    if (m < 3) {
        const float2* W = reinterpret_cast<const float2*>(m == 0 ? Wq : (m == 1 ? Wk : Wv));
        for (int e = tid; e < 64 * 128; e += 256) {
            float2 x = W[e];
            g_w2[m][e] = pack_h2(x.x, x.y);
        }
    } else {
        // dtype-robust bias gather (int64-declared indices that JAX with x64
        // disabled actually emits as int32)
        __shared__ int is32;
        const int* i32 = (const int*)idx_raw;
        if (tid == 0) is32 = 0;
        __syncthreads();
        int any = 0;
        for (int t = tid; t < N * N; t += 256)
            if ((t & 1) && i32[t] != 0) any = 1;
        if (any) is32 = 1;
        __syncthreads();
        const int stride = is32 ? 1 : 2;
        for (int t = tid; t < N * N; t += 256) {
            int e = i32[t * stride];
#pragma unroll
            for (int h = 0; h < NH; h++)
                g_bias[h * (N * N) + t] = table[e * NH + h];
        }
    }
}

// ============================ QKV GEMM (mma.sync fp16) ============================
#define PITCHB 272
#define TILE_B (128 * PITCHB)          // 34816
#define GOFF_A   0
#define GOFF_B   (TILE_B)              // B tile; staging overlays after MMAs
#define GOFF_BIAS (2 * TILE_B)
#define GSMEM_BYTES (GOFF_BIAS + 512)  // 70144

__device__ __forceinline__ void cvt_tile_h(const float2* __restrict__ src, int valid_rows,
                                           char* s_dst, int tid) {
    for (int e = tid; e < 128 * 64; e += 256) {
        int row = e >> 6, kp = e & 63;
        float2 x = (row < valid_rows) ? src[row * 64 + kp] : make_float2(0.f, 0.f);
        *reinterpret_cast<uint32_t*>(s_dst + row * PITCHB + kp * 4) = pack_h2(x.x, x.y);
    }
}

__global__ void __launch_bounds__(256, 2)
qkv_gemm_kernel(const float* __restrict__ hs,
                const float* __restrict__ bq, const float* __restrict__ bk,
                const float* __restrict__ bv, int tot)
{
    extern __shared__ char smem[];
    const int tid = threadIdx.x;
    const int warp = tid >> 5;
    const int lane = tid & 31;
    const int tileBase = blockIdx.x * 128;
    const int valid = min(128, tot - tileBase);

    float* sBias = reinterpret_cast<float*>(smem + GOFF_BIAS);
    uint32_t* staging = reinterpret_cast<uint32_t*>(smem + GOFF_B);  // [128][65] words
    const uint32_t sb = smem_u32(smem);

    cvt_tile_h(reinterpret_cast<const float2*>(hs + (size_t)tileBase * CH), valid,
               smem + GOFF_A, tid);

    const float* bs[3] = {bq, bk, bv};
    uint32_t* outs[3] = {g_q2, g_k2, g_v2};

    const uint32_t a_row = (uint32_t)((lane & 7) + ((lane >> 3) & 1) * 8);
    const uint32_t a_kb  = (uint32_t)((lane >> 4) * 16);
    const uint32_t b_row = (uint32_t)((lane & 7) + (lane >> 4) * 8);
    const uint32_t b_kb  = (uint32_t)(((lane >> 3) & 1) * 16);

    const int g  = lane >> 2;
    const int tg = lane & 3;

#pragma unroll 1
    for (int m = 0; m < 3; m++) {
        __syncthreads();  // staging reads done before B overwrite
        // copy pre-converted fp16 weight into pitched smem
        for (int e = tid; e < 128 * 64; e += 256) {
            int row = e >> 6, kp = e & 63;
            *reinterpret_cast<uint32_t*>(smem + GOFF_B + row * PITCHB + kp * 4) = g_w2[m][e];
        }
        if (tid < 128) sBias[tid] = bs[m][tid];
        __syncthreads();

        float acc[16][4];
#pragma unroll
        for (int nt = 0; nt < 16; nt++)
#pragma unroll
            for (int r = 0; r < 4; r++) acc[nt][r] = 0.f;

        const uint32_t aBase = sb + GOFF_A + (warp * 16 + a_row) * PITCHB + a_kb;
        const uint32_t bBase = sb + GOFF_B + b_row * PITCHB + b_kb;

#pragma unroll 1
        for (int ks = 0; ks < 8; ks++) {
            uint32_t ah[4];
            ldsm_x4(ah, aBase + ks * 32);
#pragma unroll
            for (int nt2 = 0; nt2 < 8; nt2++) {
                uint32_t bh[4];
                ldsm_x4(bh, bBase + (uint32_t)(nt2 * 16 * PITCHB + ks * 32));
                mma16816f16(acc[2 * nt2],     ah, bh[0], bh[1]);
                mma16816f16(acc[2 * nt2 + 1], ah, bh[2], bh[3]);
            }
        }
        __syncthreads();  // all B reads complete before staging overlays it

#pragma unroll
        for (int nt = 0; nt < 16; nt++) {
            int n = nt * 8 + 2 * tg;
            int d2 = nt * 4 + tg;
            float b0 = sBias[n], b1 = sBias[n + 1];
            staging[(warp * 16 + g) * 65 + d2]     = pack_h2(acc[nt][0] + b0, acc[nt][1] + b1);
            staging[(warp * 16 + g + 8) * 65 + d2] = pack_h2(acc[nt][2] + b0, acc[nt][3] + b1);
        }
        __syncthreads();

        uint32_t* ob = outs[m];
        for (int e = tid; e < 64 * 128; e += 256) {
            int d2 = e >> 7, tk = e & 127;
            if (tileBase + tk < tot)
                ob[(size_t)d2 * tot + tileBase + tk] = staging[tk * 65 + d2];
        }
    }
}

// ============================ attention kernel (register softmax) ============================
// smem: [0,20480) Q fp16 [h][n 64][d2 16] words pitch 20; [20480,40960) K same;
//       [40960,59392) VT fp16 [h][c 32][j 72] halves
#define AVT_OFF 40960
#define ASMEM_BYTES 59392

__global__ void __launch_bounds__(512, 2)
attn_kernel(const float* __restrict__ mask, float* __restrict__ out, int tot)
{
    extern __shared__ char smem[];
    const uint32_t sb = smem_u32(smem);
    const int b = blockIdx.x;
    const int t = threadIdx.x;
    const int lane = t & 31;
    const int warp = t >> 5;

    uint32_t* sQKw = reinterpret_cast<uint32_t*>(smem);
    __half*   sVTh = reinterpret_cast<__half*>(smem + AVT_OFF);

    const size_t tb = (size_t)b * N;
    const float* mb = mask + (size_t)b * (N * N);

    // ---- loads: Q/K word-packed per head; V transposed [c][j], j>=49 zeroed ----
    for (int e = t; e < 4096; e += 512) {
        int n = e & 63, d2 = e >> 6;
        int h = d2 >> 4, dd = d2 & 15;
        if (n < N) {
            size_t gi = (size_t)d2 * tot + tb + n;
            sQKw[h * 1280 + n * 20 + dd] = g_q2[gi];
            sQKw[5120 + h * 1280 + n * 20 + dd] = g_k2[gi];
            uint32_t vw = g_v2[gi];
            __half2 vh = *reinterpret_cast<__half2*>(&vw);
            sVTh[h * 2304 + (dd * 2) * 72 + n]     = __low2half(vh);
            sVTh[h * 2304 + (dd * 2 + 1) * 72 + n] = __high2half(vh);
        } else {
            sVTh[h * 2304 + (dd * 2) * 72 + n]     = __float2half(0.f);
            sVTh[h * 2304 + (dd * 2 + 1) * 72 + n] = __float2half(0.f);
        }
    }
    __syncthreads();

    const int h  = warp >> 2;
    const int mt = warp & 3;
    const int g  = lane >> 2;
    const int tg = lane & 3;
    const uint32_t a_row = (uint32_t)((lane & 7) + ((lane >> 3) & 1) * 8);
    const uint32_t a_kb  = (uint32_t)((lane >> 4) * 16);
    const uint32_t b_row = (uint32_t)((lane & 7) + (lane >> 4) * 8);
    const uint32_t b_kb  = (uint32_t)(((lane >> 3) & 1) * 16);
    const float rscale = 0.17677669529663687f;

    const int i0 = mt * 16 + g;
    const int i1 = i0 + 8;

    // ---- scores: Q·K^T into register fragments ----
    float sc[8][4];
#pragma unroll
    for (int nn = 0; nn < 8; nn++)
#pragma unroll
        for (int r = 0; r < 4; r++) sc[nn][r] = 0.f;
    {
        const uint32_t qbase = sb + h * 5120 + (mt * 16 + a_row) * 80 + a_kb;
        const uint32_t kbase = sb + 20480 + h * 5120 + b_row * 80 + b_kb;
#pragma unroll
        for (int kc = 0; kc < 2; kc++) {
            uint32_t ah[4];
            ldsm_x4(ah, qbase + kc * 32);
#pragma unroll
            for (int np = 0; np < 4; np++) {
                uint32_t bh[4];
                ldsm_x4(bh, kbase + (uint32_t)(np * 16 * 80) + kc * 32);
                mma16816f16(sc[2 * np],     ah, bh[0], bh[1]);
                mma16816f16(sc[2 * np + 1], ah, bh[2], bh[3]);
            }
        }
    }

    // ---- fix-up: scale + bias + mask; invalid (i>=N or j>=N) -> -1e30 (kills garbage/NaN) ----
    const float* bias_h = g_bias + h * (N * N);
    const bool i0v = i0 < N, i1v = i1 < N;
#pragma unroll
    for (int nn = 0; nn < 8; nn++) {
        int jA = nn * 8 + 2 * tg;
        int jB = jA + 1;
        bool jAv = jA < N, jBv = jB < N;
        sc[nn][0] = (i0v && jAv) ? sc[nn][0] * rscale + bias_h[i0 * N + jA] + mb[i0 * N + jA] : -1e30f;
        sc[nn][1] = (i0v && jBv) ? sc[nn][1] * rscale + bias_h[i0 * N + jB] + mb[i0 * N + jB] : -1e30f;
        sc[nn][2] = (i1v && jAv) ? sc[nn][2] * rscale + bias_h[i1 * N + jA] + mb[i1 * N + jA] : -1e30f;
        sc[nn][3] = (i1v && jBv) ? sc[nn][3] * rscale + bias_h[i1 * N + jB] + mb[i1 * N + jB] : -1e30f;
    }

    // ---- register softmax (rows i0, i1 live in 4 lanes: reduce over tg via shuffles) ----
    float mx0 = -1e30f, mx1 = -1e30f;
#pragma unroll
    for (int nn = 0; nn < 8; nn++) {
        mx0 = fmaxf(mx0, fmaxf(sc[nn][0], sc[nn][1]));
        mx1 = fmaxf(mx1, fmaxf(sc[nn][2], sc[nn][3]));
    }
    mx0 = fmaxf(mx0, __shfl_xor_sync(0xffffffffu, mx0, 1));
    mx0 = fmaxf(mx0, __shfl_xor_sync(0xffffffffu, mx0, 2));
    mx1 = fmaxf(mx1, __shfl_xor_sync(0xffffffffu, mx1, 1));
    mx1 = fmaxf(mx1, __shfl_xor_sync(0xffffffffu, mx1, 2));

    float sum0 = 0.f, sum1 = 0.f;
#pragma unroll
    for (int nn = 0; nn < 8; nn++) {
        sc[nn][0] = __expf(sc[nn][0] - mx0);
        sc[nn][1] = __expf(sc[nn][1] - mx0);
        sc[nn][2] = __expf(sc[nn][2] - mx1);
        sc[nn][3] = __expf(sc[nn][3] - mx1);
        sum0 += sc[nn][0] + sc[nn][1];
        sum1 += sc[nn][2] + sc[nn][3];
    }
    sum0 += __shfl_xor_sync(0xffffffffu, sum0, 1);
    sum0 += __shfl_xor_sync(0xffffffffu, sum0, 2);
    sum1 += __shfl_xor_sync(0xffffffffu, sum1, 1);
    sum1 += __shfl_xor_sync(0xffffffffu, sum1, 2);
    const float inv0 = 1.0f / sum0;
    const float inv1 = 1.0f / sum1;

    // ---- ctx: P (register A-fragments) x V^T; np halves to cap register use ----
    float* ob = out + tb * CH + h * 32;
    const uint32_t vbase = sb + AVT_OFF + h * 4608 + b_row * 144 + b_kb;
#pragma unroll
    for (int np = 0; np < 2; np++) {
        float ct[2][4];
#pragma unroll
        for (int q = 0; q < 2; q++)
#pragma unroll
            for (int r = 0; r < 4; r++) ct[q][r] = 0.f;
#pragma unroll
        for (int kc = 0; kc < 4; kc++) {
            uint32_t a[4];
            a[0] = pack_h2(sc[2 * kc][0] * inv0,     sc[2 * kc][1] * inv0);
            a[1] = pack_h2(sc[2 * kc][2] * inv1,     sc[2 * kc][3] * inv1);
            a[2] = pack_h2(sc[2 * kc + 1][0] * inv0, sc[2 * kc + 1][1] * inv0);
            a[3] = pack_h2(sc[2 * kc + 1][2] * inv1, sc[2 * kc + 1][3] * inv1);
            uint32_t bh[4];
            ldsm_x4(bh, vbase + (uint32_t)(np * 16 * 144) + kc * 32);
            mma16816f16(ct[0], a, bh[0], bh[1]);
            mma16816f16(ct[1], a, bh[2], bh[3]);
        }
#pragma unroll
        for (int q = 0; q < 2; q++) {
            int c = np * 16 + q * 8 + 2 * tg;
            if (i0v)
                *reinterpret_cast<float2*>(&ob[i0 * CH + c]) = make_float2(ct[q][0], ct[q][1]);
            if (i1v)
                *reinterpret_cast<float2*>(&ob[i1 * CH + c]) = make_float2(ct[q][2], ct[q][3]);
        }
    }
}

// ============================ launch ============================
extern "C" void kernel_launch(void* const* d_in, const int* in_sizes, int n_in,
                              void* d_out, int out_size) {
    const float* hs    = (const float*)d_in[0];
    const float* mask  = (const float*)d_in[1];
    const float* Wq    = (const float*)d_in[2];
    const float* bq    = (const float*)d_in[3];
    const float* Wk    = (const float*)d_in[4];
    const float* bk    = (const float*)d_in[5];
    const float* Wv    = (const float*)d_in[6];
    const float* bv    = (const float*)d_in[7];
    const float* table = (const float*)d_in[8];
    const void*  idx   = (const void*)d_in[9];
    float* out = (float*)d_out;

    int B = in_sizes[0] / (N * CH);
    int tot = B * N;

    cudaFuncSetAttribute(qkv_gemm_kernel, cudaFuncAttributeMaxDynamicSharedMemorySize,
                         GSMEM_BYTES);
    cudaFuncSetAttribute(attn_kernel, cudaFuncAttributeMaxDynamicSharedMemorySize,
                         ASMEM_BYTES);

    prep_kernel<<<4, 256>>>(Wq, Wk, Wv, table, idx);

    int tiles = (tot + 127) / 128;
    qkv_gemm_kernel<<<tiles, 256, GSMEM_BYTES>>>(hs, bq, bk, bv, tot);
    attn_kernel<<<B, 512, ASMEM_BYTES>>>(mask, out, tot);
}